// round 11
// baseline (speedup 1.0000x reference)
#include <cuda_runtime.h>
#include <math.h>
#include <stdint.h>

#define B 8
#define C 256
#define H 128
#define W 128
#define OH 65
#define OW 65
#define HW (H*W)          // 16384
#define OHW (OH*OW)       // 4225
#define NPIX (B*OHW)      // 33800
#define SPLIT 8           // channel splits in norm kernel
#define CPS (C/SPLIT)     // 32 channels per split
#define CSPLIT 4          // channel quarters in gather
#define CPW 8             // channels per warp in gather (8 warps * 8 * 4 = 256)
#define DEPTH 3           // cp.async pipeline stages
#define ROWF 132          // padded smem row floats

// Scratch: device globals
__device__ float g_part[SPLIT*B*HW];     // 4 MB
__device__ float g_norm[B*HW];           // 512 KB
__device__ float g_wts[9*NPIX];          // ~1.22 MB, layout [k][pixel]

// ---------------------------------------------------------------------------
// Kernel 1: partial channel sum-of-squares (proven ~7.9 TB/s config).
// ---------------------------------------------------------------------------
__global__ __launch_bounds__(128) void norm_part_kernel(const float* __restrict__ x) {
    int t   = threadIdx.x;
    int w4  = t & 31;
    int hl  = t >> 5;
    int bh4 = blockIdx.x;
    int b   = bh4 >> 5;
    int h   = ((bh4 & 31) << 2) + hl;
    int c0  = blockIdx.y * CPS;

    const float4* p = (const float4*)(x + ((size_t)(b * C + c0)) * HW + (size_t)h * W) + w4;

    float sx = 0.f, sy = 0.f, sz = 0.f, sw = 0.f;
    #pragma unroll 8
    for (int c = 0; c < CPS; c++) {
        float4 v = p[(size_t)c * (HW / 4)];
        sx = fmaf(v.x, v.x, sx);
        sy = fmaf(v.y, v.y, sy);
        sz = fmaf(v.z, v.z, sz);
        sw = fmaf(v.w, v.w, sw);
    }

    float4 o = make_float4(sx, sy, sz, sw);
    ((float4*)g_part)[(size_t)blockIdx.y * (B * HW / 4) + ((size_t)(b * H + h) * W) / 4 + w4] = o;
}

// ---------------------------------------------------------------------------
// Kernel 2: reduce partials + sqrt -> g_norm.
// ---------------------------------------------------------------------------
__global__ __launch_bounds__(256) void norm_reduce_kernel() {
    int i = blockIdx.x * blockDim.x + threadIdx.x;
    if (i >= B * HW / 4) return;
    const float4* p = (const float4*)g_part;
    float4 a = p[i];
    #pragma unroll
    for (int s = 1; s < SPLIT; s++) {
        float4 v = p[(size_t)s * (B * HW / 4) + i];
        a.x += v.x; a.y += v.y; a.z += v.z; a.w += v.w;
    }
    a.x = sqrtf(a.x); a.y = sqrtf(a.y); a.z = sqrtf(a.z); a.w = sqrtf(a.w);
    ((float4*)g_norm)[i] = a;
}

// ---------------------------------------------------------------------------
// Kernel 3: softmax weights, layout [k][pixel].
// ---------------------------------------------------------------------------
__global__ __launch_bounds__(256) void wts_kernel() {
    int idx = blockIdx.x * blockDim.x + threadIdx.x;
    if (idx >= NPIX) return;
    int ox = idx % OW;
    int t  = idx / OW;
    int oy = t % OH;
    int b  = t / OH;

    int iy0 = 2 * oy - 2;
    int ix0 = 2 * ox - 2;

    float v[9];
    #pragma unroll
    for (int i = 0; i < 3; i++) {
        int iy = iy0 + i;
        bool rok = (unsigned)iy < (unsigned)H;
        #pragma unroll
        for (int j = 0; j < 3; j++) {
            int ix = ix0 + j;
            bool ok = rok && ((unsigned)ix < (unsigned)W);
            v[i * 3 + j] = ok ? g_norm[(b * H + iy) * W + ix] : 0.f;
        }
    }

    float m = v[0];
    #pragma unroll
    for (int k = 1; k < 9; k++) m = fmaxf(m, v[k]);

    float e[9], sum = 0.f;
    #pragma unroll
    for (int k = 0; k < 9; k++) { e[k] = expf(v[k] - m); sum += e[k]; }
    float inv = 1.f / sum;

    #pragma unroll
    for (int k = 0; k < 9; k++) g_wts[k * NPIX + idx] = e[k] * inv;
}

// ---------------------------------------------------------------------------
// cp.async helpers
// ---------------------------------------------------------------------------
__device__ __forceinline__ void cp16(uint32_t saddr, const void* gaddr) {
    asm volatile("cp.async.cg.shared.global [%0], [%1], 16;" :: "r"(saddr), "l"(gaddr));
}
__device__ __forceinline__ void cp_commit() {
    asm volatile("cp.async.commit_group;");
}
__device__ __forceinline__ void cp_wait() {
    asm volatile("cp.async.wait_group %0;" :: "n"(DEPTH - 1));
}

// ---------------------------------------------------------------------------
// Kernel 4: cp.async-pipelined register-stencil gather.
// Block = (b, channel-quarter, oy), 256 thr, 8 warps. Warp owns channel
// c = ci*8+warp within its quarter; DEPTH=3 channel-stages of 3 rows x 512B
// live in smem via LDGSTS. Compute: LDS.128 + LDS.64 stencil, per-warp
// pipeline (no block barriers).
// ---------------------------------------------------------------------------
__global__ __launch_bounds__(256) void gather_kernel(const float* __restrict__ x,
                                                     float* __restrict__ out) {
    __shared__ float sm[8][DEPTH][3][ROWF];      // 38,016 B

    int bid = blockIdx.x;                 // ((b*CSPLIT+cs)*OH + oy)
    int oy  = bid % OH;
    int t2  = bid / OH;
    int cs  = t2 & (CSPLIT - 1);
    int b   = t2 / CSPLIT;

    int warp = threadIdx.x >> 5;
    int lane = threadIdx.x & 31;

    // ---- Weights for this thread's pixels ----
    int pixb = (b * OH + oy) * OW;
    float wA[9], wB[9], wC[9];
    #pragma unroll
    for (int k = 0; k < 9; k++) {
        wA[k] = g_wts[k * NPIX + pixb + 2 * lane];       // ox0 = 2*lane
        wB[k] = g_wts[k * NPIX + pixb + 2 * lane + 1];   // ox1 = 2*lane+1
        wC[k] = g_wts[k * NPIX + pixb + 64];             // ox2 = 64 (lane31)
    }
    if (lane == 0) {
        #pragma unroll
        for (int i = 0; i < 3; i++) { wA[i*3+0] = 0.f; wA[i*3+1] = 0.f; }
    }
    #pragma unroll
    for (int i = 0; i < 3; i++) wC[i*3+2] = 0.f;         // col 128 is pad

    // Row clamps + pad zeroing.
    int iy0 = 2 * oy - 2;
    int iyv[3];
    #pragma unroll
    for (int i = 0; i < 3; i++) {
        int iy = iy0 + i;
        if (iy < 0 || iy >= H) {
            iy = iy < 0 ? 0 : H - 1;
            wA[i*3] = wA[i*3+1] = wA[i*3+2] = 0.f;
            wB[i*3] = wB[i*3+1] = wB[i*3+2] = 0.f;
            wC[i*3] = wC[i*3+1] = wC[i*3+2] = 0.f;
        }
        iyv[i] = iy;
    }

    const float* xbase = x + (size_t)(b * C + cs * (C / CSPLIT)) * HW;
    float* obase = out + (size_t)(b * C + cs * (C / CSPLIT)) * OHW + (size_t)oy * OW;

    uint32_t sb = (uint32_t)__cvta_generic_to_shared(&sm[warp][0][0][0]);
    int cm2 = lane == 0 ? 0 : 4 * lane - 2;   // safe float2 offset (weights zeroed)

    // ---- Prologue: fill DEPTH stages ----
    #pragma unroll
    for (int s = 0; s < DEPTH; s++) {
        const float* rb = xbase + (size_t)(s * 8 + warp) * HW;
        #pragma unroll
        for (int i = 0; i < 3; i++)
            cp16(sb + (uint32_t)((s * 3 + i) * ROWF + lane * 4) * 4,
                 rb + iyv[i] * W + lane * 4);
        cp_commit();
    }

    // ---- Main loop ----
    for (int ci = 0; ci < CPW; ci++) {
        int c  = ci * 8 + warp;
        int st = ci % DEPTH;

        cp_wait();
        __syncwarp();

        const float (*rowp)[ROWF] = sm[warp][st];

        float acc0 = 0.f, acc1 = 0.f, acc2 = 0.f;
        #pragma unroll
        for (int i = 0; i < 3; i++) {
            float4 v  = *(const float4*)&rowp[i][4 * lane];  // cols 4l..4l+3
            float2 pv = *(const float2*)&rowp[i][cm2];       // cols 4l-2,4l-1

            acc0 = fmaf(wA[i*3+0], pv.x, acc0);   // ox0: 4l-2,4l-1,4l
            acc0 = fmaf(wA[i*3+1], pv.y, acc0);
            acc0 = fmaf(wA[i*3+2], v.x,  acc0);
            acc1 = fmaf(wB[i*3+0], v.x,  acc1);   // ox1: 4l,4l+1,4l+2
            acc1 = fmaf(wB[i*3+1], v.y,  acc1);
            acc1 = fmaf(wB[i*3+2], v.z,  acc1);
            acc2 = fmaf(wC[i*3+0], v.z,  acc2);   // ox=64: 126,127 (lane31)
            acc2 = fmaf(wC[i*3+1], v.w,  acc2);
        }

        __syncwarp();   // all lanes done reading stage before refill lands

        if (ci + DEPTH < CPW) {
            const float* rb = xbase + (size_t)((ci + DEPTH) * 8 + warp) * HW;
            #pragma unroll
            for (int i = 0; i < 3; i++)
                cp16(sb + (uint32_t)((st * 3 + i) * ROWF + lane * 4) * 4,
                     rb + iyv[i] * W + lane * 4);
        }
        cp_commit();    // unconditional: keeps group accounting uniform

        float* orow = obase + (size_t)c * OHW;
        orow[2 * lane]     = acc0;
        orow[2 * lane + 1] = acc1;
        if (lane == 31) orow[64] = acc2;
    }
}

// ---------------------------------------------------------------------------
extern "C" void kernel_launch(void* const* d_in, const int* in_sizes, int n_in,
                              void* d_out, int out_size) {
    const float* x = (const float*)d_in[0];
    float* out = (float*)d_out;

    dim3 g1(B * H / 4, SPLIT);                   // 2048 blocks
    norm_part_kernel<<<g1, 128>>>(x);

    int n2 = B * HW / 4;
    norm_reduce_kernel<<<(n2 + 255) / 256, 256>>>();

    wts_kernel<<<(NPIX + 255) / 256, 256>>>();

    int n4 = B * CSPLIT * OH;                    // 2080 blocks
    gather_kernel<<<n4, 256>>>(x, out);
}